// round 11
// baseline (speedup 1.0000x reference)
#include <cuda_runtime.h>
#include <cuda_bf16.h>
#include <cstdint>

// XLSTM social pooling as dense masked GEMM via mma.sync (HMMA bf16, sm_103-legal).
//
// Per CTA (grid = 64 batches x 2 i-halves, 256 threads):
//   D[i(128), h(128)] = sum_{k=0..511} A[i,k] * B[k,h]
//   where k<256: A = mask[i,j=k],      B = bf16_hi(H[j,h])
//         k>=256: A = mask[i,j=k-256], B = bf16_lo residual
//   -> exact-mask bf16 hi/lo split, single pass, rel_err ~1e-5.
//
// Mask kept as bitmasks (128 x 8 u32); A fragments synthesized in registers.
// H staged to swizzled smem ([512][128] bf16); B fragments via ldmatrix.trans.
// 8 warps: warp (wi,wh) owns D tile 32i x 64h = 2x8 m16n8k16 accumulators.

#define NA   256
#define NB   64
#define SEQL 20
#define HID  128

#define THREADS 256

// smem layout (bytes from dynamic base; base is >=1024-aligned)
#define PS_OFF   0                    // float2[256]   (2048 B)
#define CNT_OFF  2048                 // float[128]    (512 B)
#define MSK_OFF  2560                 // u32[128][8]   (4096 B)
#define H_OFF    8192                 // bf16[512][128] rows 256B, swizzled (128 KB)
#define SMEM_BYTES (H_OFF + 512 * 256)

__device__ __forceinline__ uint32_t smem_u32(const void* p) {
    uint32_t a;
    asm("{ .reg .u64 t; cvta.to.shared.u64 t, %1; cvt.u32.u64 %0, t; }" : "=r"(a) : "l"(p));
    return a;
}

__device__ __forceinline__ void ldsm4t(uint32_t& r0, uint32_t& r1, uint32_t& r2,
                                       uint32_t& r3, uint32_t addr) {
    asm volatile("ldmatrix.sync.aligned.m8n8.x4.trans.shared.b16 {%0,%1,%2,%3}, [%4];"
                 : "=r"(r0), "=r"(r1), "=r"(r2), "=r"(r3) : "r"(addr));
}

__device__ __forceinline__ void mma_bf16(float* c, const uint32_t* a,
                                         uint32_t b0, uint32_t b1) {
    asm volatile(
        "mma.sync.aligned.m16n8k16.row.col.f32.bf16.bf16.f32 "
        "{%0,%1,%2,%3}, {%4,%5,%6,%7}, {%8,%9}, {%0,%1,%2,%3};"
        : "+f"(c[0]), "+f"(c[1]), "+f"(c[2]), "+f"(c[3])
        : "r"(a[0]), "r"(a[1]), "r"(a[2]), "r"(a[3]), "r"(b0), "r"(b1));
}

// 2 mask bits -> packed bf16x2 {lo half = bit0 ? 1.0 : 0, hi half = bit1 ? 1.0 : 0}
__device__ __forceinline__ uint32_t bits2bf(uint32_t w, int sh) {
    const uint32_t p = (w >> sh) & 3u;
    return (p & 1u) * 0x3F80u + (p >> 1) * 0x3F800000u;
}

__global__ __launch_bounds__(THREADS, 1)
void social_pool_hmma(const float* __restrict__ hidden,
                      const float* __restrict__ pos,
                      const float* __restrict__ radius_ptr,
                      float* __restrict__ out)
{
    extern __shared__ char smem[];
    const uint32_t sb = smem_u32(smem);
    float2*   ps   = (float2*)(smem + PS_OFF);
    float*    cnts = (float*)(smem + CNT_OFF);
    uint32_t* msk  = (uint32_t*)(smem + MSK_OFF);   // [128][8]

    const int tid  = threadIdx.x;
    const int wid  = tid >> 5;
    const int lane = tid & 31;
    const int b     = blockIdx.x >> 1;
    const int ihalf = blockIdx.x & 1;

    // --- stage positions (last timestep): 1 agent per thread ---
    {
        const float* pp = pos + ((size_t)(tid * NB + b) * SEQL + (SEQL - 1)) * 2;
        ps[tid] = make_float2(pp[0], pp[1]);
    }
    __syncthreads();

    const float r  = *radius_ptr;
    const float r2 = r * r;

    // --- phase 2: mask bitmasks + counts. warp w -> i-local rows [w*16, w*16+16) ---
    {
        float2 pjr[8];
        #pragma unroll
        for (int g2 = 0; g2 < 8; g2++) pjr[g2] = ps[g2 * 32 + lane];

        for (int k = 0; k < 16; k++) {
            const int il = wid * 16 + k;
            const int ig = ihalf * 128 + il;
            const float2 pi = ps[ig];
            int cnt = 0;
            #pragma unroll
            for (int g2 = 0; g2 < 8; g2++) {
                const int jg = g2 * 32 + lane;
                const float dx = pi.x - pjr[g2].x;
                const float dy = pi.y - pjr[g2].y;
                const bool ok = (dx * dx + dy * dy <= r2) && (jg != ig);
                const unsigned bm = __ballot_sync(0xffffffffu, ok);
                cnt += __popc(bm);
                if (lane == 0) msk[il * 8 + g2] = bm;
            }
            if (lane == 0) cnts[il] = 1.0f / fmaxf((float)cnt, 1.0f);
        }
    }

    // --- phase 3: stage H hi/lo bf16, swizzled. warp w -> j rows [w*32, w*32+32) ---
    for (int k = 0; k < 32; k++) {
        const int j = wid * 32 + k;
        const float4 v = *(const float4*)
            (hidden + ((size_t)(j * NB + b) * SEQL + (SEQL - 1)) * HID + lane * 4);

        const __nv_bfloat162 h01 = __float22bfloat162_rn(make_float2(v.x, v.y));
        const __nv_bfloat162 h23 = __float22bfloat162_rn(make_float2(v.z, v.w));
        const float2 b01 = __bfloat1622float2(h01);
        const float2 b23 = __bfloat1622float2(h23);
        const __nv_bfloat162 l01 =
            __float22bfloat162_rn(make_float2(v.x - b01.x, v.y - b01.y));
        const __nv_bfloat162 l23 =
            __float22bfloat162_rn(make_float2(v.z - b23.x, v.w - b23.y));

        const uint32_t col = ((uint32_t)(lane * 8)) ^ (((uint32_t)(j & 7)) << 4);
        uint2 hv, lv;
        hv.x = *(const uint32_t*)&h01;  hv.y = *(const uint32_t*)&h23;
        lv.x = *(const uint32_t*)&l01;  lv.y = *(const uint32_t*)&l23;
        *(uint2*)(smem + H_OFF + (size_t)j * 256 + col) = hv;
        *(uint2*)(smem + H_OFF + (size_t)(j + 256) * 256 + col) = lv;
    }
    __syncthreads();

    // --- phase 4: GEMM. warp (wi, wh): D tile rows ibase..+32, cols hbase..+64 ---
    const int wi = wid >> 1, wh = wid & 1;
    const int ibase = wi * 32, hbase = wh * 64;
    const int g = lane >> 2, t = lane & 3;
    const int lr = lane & 7, lmi = lane >> 3;

    float acc[2][8][4];
    #pragma unroll
    for (int mt = 0; mt < 2; mt++)
        #pragma unroll
        for (int nt = 0; nt < 8; nt++)
            #pragma unroll
            for (int c = 0; c < 4; c++) acc[mt][nt][c] = 0.0f;

    for (int s = 0; s < 32; s++) {
        const int half = s >> 4;
        const int j0   = (s & 15) * 16;                 // mask j base
        const int jj   = half * 256 + j0 + (lmi & 1) * 8 + lr;

        // B fragments: 4x ldmatrix.x4.trans, covering n = hbase..hbase+63
        uint32_t bf[4][4];
        #pragma unroll
        for (int np = 0; np < 4; np++) {
            const uint32_t colb =
                ((uint32_t)((hbase + np * 16 + (lmi >> 1) * 8) * 2)) ^
                (((uint32_t)lr) << 4);
            const uint32_t addr = sb + H_OFF + (uint32_t)jj * 256 + colb;
            ldsm4t(bf[np][0], bf[np][1], bf[np][2], bf[np][3], addr);
        }

        // A fragments from bitmasks
        const int jw = j0 >> 5;          // 0..7
        const int sh = (j0 & 31) + 2 * t;
        uint32_t a[2][4];
        #pragma unroll
        for (int mt = 0; mt < 2; mt++) {
            const int r0 = ibase + mt * 16 + g;
            const uint32_t w0 = msk[r0 * 8 + jw];
            const uint32_t w1 = msk[(r0 + 8) * 8 + jw];
            a[mt][0] = bits2bf(w0, sh);
            a[mt][1] = bits2bf(w1, sh);
            a[mt][2] = bits2bf(w0, sh + 8);
            a[mt][3] = bits2bf(w1, sh + 8);
        }

        #pragma unroll
        for (int mt = 0; mt < 2; mt++)
            #pragma unroll
            for (int nt = 0; nt < 8; nt++)
                mma_bf16(acc[mt][nt], a[mt], bf[nt >> 1][(nt & 1) * 2],
                         bf[nt >> 1][(nt & 1) * 2 + 1]);
    }

    // --- epilogue: scale by 1/count, write out ---
    #pragma unroll
    for (int mt = 0; mt < 2; mt++) {
        const int il0 = ibase + mt * 16 + g;
        const float s0 = cnts[il0];
        const float s1 = cnts[il0 + 8];
        const int ig0 = ihalf * 128 + il0;
        #pragma unroll
        for (int nt = 0; nt < 8; nt++) {
            const int h = hbase + nt * 8 + 2 * t;
            float2 v0 = make_float2(acc[mt][nt][0] * s0, acc[mt][nt][1] * s0);
            float2 v1 = make_float2(acc[mt][nt][2] * s1, acc[mt][nt][3] * s1);
            *(float2*)(out + ((size_t)ig0 * NB + b) * HID + h) = v0;
            *(float2*)(out + ((size_t)(ig0 + 8) * NB + b) * HID + h) = v1;
        }
    }
}

extern "C" void kernel_launch(void* const* d_in, const int* in_sizes, int n_in,
                              void* d_out, int out_size)
{
    const float* hidden = (const float*)d_in[0];   // (256,64,20,128) f32
    const float* pos    = (const float*)d_in[1];   // (256,64,20,2)  f32
    const float* radius = (const float*)d_in[2];   // scalar f32
    float* out = (float*)d_out;                    // (256,64,128)   f32

    cudaFuncSetAttribute(social_pool_hmma,
                         cudaFuncAttributeMaxDynamicSharedMemorySize,
                         SMEM_BYTES);

    social_pool_hmma<<<NB * 2, THREADS, SMEM_BYTES>>>(hidden, pos, radius, out);
}